// round 16
// baseline (speedup 1.0000x reference)
#include <cuda_runtime.h>
#include <cuda_fp16.h>
#include <cstdint>

#define C 128
#define N_MAX 16384
#define E_MAX 1100000
#define CAP 256

// Static scratch (no allocs allowed)
__device__ int g_idx64;
__device__ int g_cnt[N_MAX];
__device__ int g_ssrc[N_MAX * CAP];           // bucketed src ids
__device__ int g_ovf_cnt;
__device__ long long g_ovf[E_MAX];            // overflow edges (dst<<32 | src)
__device__ __half g_xh[N_MAX * C];            // fp16 copy of x for gather stream

__global__ void detect_idx_kernel(const void* __restrict__ ei, int n_nodes) {
    if (threadIdx.x == 0 && blockIdx.x == 0) {
        const long long* p = (const long long*)ei;
        int ok = 1;
        #pragma unroll
        for (int i = 0; i < 16; i++) {
            long long v = p[i];
            if (v < 0 || v >= (long long)n_nodes) { ok = 0; }
        }
        g_idx64 = ok;
    }
}

// Merged prep: fp32->fp16 convert of x, then bucket edges by destination.
__global__ void prep_kernel(const float* __restrict__ x,
                            const void* __restrict__ ei,
                            int n_edges, int n_nodes, int n_f4) {
    __shared__ int s_idx64;
    if (threadIdx.x == 0) {
        const long long* p = (const long long*)ei;
        int ok = 1;
        #pragma unroll
        for (int i = 0; i < 16; i++) {
            long long v = p[i];
            if (v < 0 || v >= (long long)n_nodes) { ok = 0; }
        }
        s_idx64 = ok;
    }

    int gid = blockIdx.x * blockDim.x + threadIdx.x;
    int stride = gridDim.x * blockDim.x;

    for (int i = gid; i < n_f4; i += stride) {
        float4 v = __ldg((const float4*)x + i);
        __half2 h0 = __floats2half2_rn(v.x, v.y);
        __half2 h1 = __floats2half2_rn(v.z, v.w);
        uint2 u;
        u.x = *reinterpret_cast<unsigned*>(&h0);
        u.y = *reinterpret_cast<unsigned*>(&h1);
        ((uint2*)g_xh)[i] = u;
    }

    __syncthreads();
    const int idx64 = s_idx64;

    const long long* p64 = (const long long*)ei;
    const int*       p32 = (const int*)ei;
    for (int e = gid; e < n_edges; e += stride) {
        int s, d;
        if (idx64) {
            s = (int)__ldg(p64 + e);
            d = (int)__ldg(p64 + n_edges + e);
        } else {
            s = __ldg(p32 + e);
            d = __ldg(p32 + n_edges + e);
        }
        int pos = atomicAdd(&g_cnt[d], 1);
        if (pos < CAP) {
            g_ssrc[d * CAP + pos] = s;
        } else {
            int o = atomicAdd(&g_ovf_cnt, 1);
            g_ovf[o] = ((long long)d << 32) | (unsigned)s;
        }
    }
}

// Transposed 4-value warp reduction: 10 SHFL for 4 independent sums.
__device__ __forceinline__ void reduce4(float p0, float p1, float p2, float p3,
                                        float& A0, float& A1, float& A2, float& A3,
                                        int lane)
{
    const unsigned FULL = 0xffffffffu;
    bool lo16 = (lane & 16) == 0;
    float q01 = (lo16 ? p0 : p1) + __shfl_xor_sync(FULL, lo16 ? p1 : p0, 16);
    float q23 = (lo16 ? p2 : p3) + __shfl_xor_sync(FULL, lo16 ? p3 : p2, 16);
    bool lo8 = (lane & 8) == 0;
    float r = (lo8 ? q01 : q23) + __shfl_xor_sync(FULL, lo8 ? q23 : q01, 8);
    r += __shfl_xor_sync(FULL, r, 4);
    r += __shfl_xor_sync(FULL, r, 2);
    r += __shfl_xor_sync(FULL, r, 1);
    A0 = __shfl_sync(FULL, r, 0);
    A2 = __shfl_sync(FULL, r, 8);
    A1 = __shfl_sync(FULL, r, 16);
    A3 = __shfl_sync(FULL, r, 24);
}

// One warp per destination node (R11/R14 geometry — proven best). Pipelined
// main loop over FULL quads; 0-3 remainder edges in a plain epilogue.
// __launch_bounds__(256, 5): cap regs at 51 to lift occupancy 50% -> 62.5%.
__global__ __launch_bounds__(256, 5) void gather_kernel(
    const float* __restrict__ x,
    const float* __restrict__ W2,
    const float* __restrict__ W3,
    float* __restrict__ out,
    int n_nodes)
{
    const int lane = threadIdx.x & 31;
    const int j = (int)((blockIdx.x * (unsigned)blockDim.x + threadIdx.x) >> 5);
    if (j >= n_nodes) return;
    const unsigned FULL = 0xffffffffu;

    float4 xj = __ldg((const float4*)(x + (long long)j * C) + lane);
    float4 w3 = __ldg((const float4*)W3 + lane);
    float4 w3xj;
    w3xj.x = w3.x * xj.x; w3xj.y = w3.y * xj.y;
    w3xj.z = w3.z * xj.z; w3xj.w = w3.w * xj.w;

    float4 acc = make_float4(0.f, 0.f, 0.f, 0.f);

    const int deg_raw = __ldg(&g_cnt[j]);
    const int deg = (deg_raw > CAP) ? CAP : deg_raw;
    const int deg4 = deg & ~3;               // full quads
    const int* bucket = &g_ssrc[j * CAP];

    if (deg4 > 0) {
        // Prologue: indices for iter 0 and iter 1; rows for iter 0.
        int4 sv_nxt = __ldg((const int4*)bucket);
        uint2 uc0 = __ldg((const uint2*)(g_xh + (long long)sv_nxt.x * C) + lane);
        uint2 uc1 = __ldg((const uint2*)(g_xh + (long long)sv_nxt.y * C) + lane);
        uint2 uc2 = __ldg((const uint2*)(g_xh + (long long)sv_nxt.z * C) + lane);
        uint2 uc3 = __ldg((const uint2*)(g_xh + (long long)sv_nxt.w * C) + lane);
        sv_nxt = __ldg((const int4*)(bucket + ((4 < deg4) ? 4 : 0)));

        for (int i = 0; i < deg4; i += 4) {
            int pf = (i + 8 < deg4) ? (i + 8) : 0;
            int4 sv_fut = __ldg((const int4*)(bucket + pf));

            uint2 un0 = __ldg((const uint2*)(g_xh + (long long)sv_nxt.x * C) + lane);
            uint2 un1 = __ldg((const uint2*)(g_xh + (long long)sv_nxt.y * C) + lane);
            uint2 un2 = __ldg((const uint2*)(g_xh + (long long)sv_nxt.z * C) + lane);
            uint2 un3 = __ldg((const uint2*)(g_xh + (long long)sv_nxt.w * C) + lane);

            float2 a0 = __half22float2(*(__half2*)&uc0.x), b0 = __half22float2(*(__half2*)&uc0.y);
            float2 a1 = __half22float2(*(__half2*)&uc1.x), b1 = __half22float2(*(__half2*)&uc1.y);
            float2 a2 = __half22float2(*(__half2*)&uc2.x), b2 = __half22float2(*(__half2*)&uc2.y);
            float2 a3 = __half22float2(*(__half2*)&uc3.x), b3 = __half22float2(*(__half2*)&uc3.y);

            float p0 = a0.x * w3xj.x + a0.y * w3xj.y + b0.x * w3xj.z + b0.y * w3xj.w;
            float p1 = a1.x * w3xj.x + a1.y * w3xj.y + b1.x * w3xj.z + b1.y * w3xj.w;
            float p2 = a2.x * w3xj.x + a2.y * w3xj.y + b2.x * w3xj.z + b2.y * w3xj.w;
            float p3 = a3.x * w3xj.x + a3.y * w3xj.y + b3.x * w3xj.z + b3.y * w3xj.w;

            float A0, A1, A2, A3;
            reduce4(p0, p1, p2, p3, A0, A1, A2, A3, lane);

            // No tail masking — every edge in this loop is valid.
            acc.x += A0 * a0.x + A1 * a1.x + A2 * a2.x + A3 * a3.x;
            acc.y += A0 * a0.y + A1 * a1.y + A2 * a2.y + A3 * a3.y;
            acc.z += A0 * b0.x + A1 * b1.x + A2 * b2.x + A3 * b3.x;
            acc.w += A0 * b0.y + A1 * b1.y + A2 * b2.y + A3 * b3.y;

            uc0 = un0; uc1 = un1; uc2 = un2; uc3 = un3;
            sv_nxt = sv_fut;
        }
    }

    // Remainder: 0-3 edges, plain butterfly per edge.
    for (int i = deg4; i < deg; i++) {
        int s = __ldg(bucket + i);
        uint2 u0 = __ldg((const uint2*)(g_xh + (long long)s * C) + lane);
        float2 a0 = __half22float2(*(__half2*)&u0.x), b0 = __half22float2(*(__half2*)&u0.y);
        float p0 = a0.x * w3xj.x + a0.y * w3xj.y + b0.x * w3xj.z + b0.y * w3xj.w;
        #pragma unroll
        for (int o = 16; o > 0; o >>= 1)
            p0 += __shfl_xor_sync(FULL, p0, o);
        acc.x += p0 * a0.x; acc.y += p0 * a0.y;
        acc.z += p0 * b0.x; acc.w += p0 * b0.y;
    }

    // Rare: node overflowed CAP — its warp scans the overflow list.
    if (deg_raw > CAP) {
        int n = g_ovf_cnt;
        for (int e2 = 0; e2 < n; e2++) {
            long long pk = g_ovf[e2];
            if ((int)(pk >> 32) != j) continue;
            int s = (int)(unsigned)(pk & 0xffffffffLL);
            uint2 u0 = __ldg((const uint2*)(g_xh + (long long)s * C) + lane);
            float2 a0 = __half22float2(*(__half2*)&u0.x), b0 = __half22float2(*(__half2*)&u0.y);
            float p0 = a0.x * w3xj.x + a0.y * w3xj.y + b0.x * w3xj.z + b0.y * w3xj.w;
            #pragma unroll
            for (int o = 16; o > 0; o >>= 1)
                p0 += __shfl_xor_sync(FULL, p0, o);
            acc.x += p0 * a0.x; acc.y += p0 * a0.y;
            acc.z += p0 * b0.x; acc.w += p0 * b0.y;
        }
    }

    float4 w2 = __ldg((const float4*)W2 + lane);
    float4 r;
    r.x = acc.x * w2.x; r.y = acc.y * w2.y;
    r.z = acc.z * w2.z; r.w = acc.w * w2.w;
    ((float4*)(out + (long long)j * C))[lane] = r;
}

// ---------------- Fallback (R5 kernel) for unexpected shapes ----------------
__global__ __launch_bounds__(256, 4) void edge_scatter_kernel(
    const float* __restrict__ x, const void* __restrict__ ei,
    const float* __restrict__ W2, const float* __restrict__ W3,
    float* __restrict__ out, int n_edges)
{
    const int lane = threadIdx.x & 31;
    const int t = lane & 7;
    const int grp = lane >> 3;
    const int warp_id = (int)((blockIdx.x * (unsigned)blockDim.x + threadIdx.x) >> 5);
    const int n_warps = (int)((gridDim.x * (unsigned)blockDim.x) >> 5);

    float4 w2v[4], w3v[4];
    #pragma unroll
    for (int k = 0; k < 4; k++) {
        w3v[k] = __ldg((const float4*)W3 + (t + 8 * k));
        w2v[k] = __ldg((const float4*)W2 + (t + 8 * k));
    }
    const int idx64 = g_idx64;
    const long long* p64 = (const long long*)ei;
    const int*       p32 = (const int*)ei;

    for (int base = warp_id * 4; base < n_edges; base += n_warps * 4) {
        int e = base + grp;
        bool valid = (e < n_edges);
        int ec = valid ? e : (n_edges - 1);
        long long src, dst;
        if (idx64) { src = __ldg(p64 + ec); dst = __ldg(p64 + n_edges + ec); }
        else { src = (long long)__ldg(p32 + ec); dst = (long long)__ldg(p32 + n_edges + ec); }

        const float4* srow = (const float4*)(x + src * C);
        const float4* drow = (const float4*)(x + dst * C);
        float4 vs[4], vd[4];
        #pragma unroll
        for (int k = 0; k < 4; k++) vs[k] = __ldg(srow + (t + 8 * k));
        #pragma unroll
        for (int k = 0; k < 4; k++) vd[k] = __ldg(drow + (t + 8 * k));

        float part = 0.f;
        #pragma unroll
        for (int k = 0; k < 4; k++)
            part += vs[k].x * w3v[k].x * vd[k].x + vs[k].y * w3v[k].y * vd[k].y
                  + vs[k].z * w3v[k].z * vd[k].z + vs[k].w * w3v[k].w * vd[k].w;
        part += __shfl_xor_sync(0xffffffffu, part, 4);
        part += __shfl_xor_sync(0xffffffffu, part, 2);
        part += __shfl_xor_sync(0xffffffffu, part, 1);

        if (valid) {
            float* op = out + dst * C;
            #pragma unroll
            for (int k = 0; k < 4; k++) {
                float4 r;
                r.x = part * vs[k].x * w2v[k].x; r.y = part * vs[k].y * w2v[k].y;
                r.z = part * vs[k].z * w2v[k].z; r.w = part * vs[k].w * w2v[k].w;
                asm volatile("red.global.add.v4.f32 [%0], {%1,%2,%3,%4};"
                             :: "l"(op + (t + 8 * k) * 4),
                                "f"(r.x), "f"(r.y), "f"(r.z), "f"(r.w) : "memory");
            }
        }
    }
}

extern "C" void kernel_launch(void* const* d_in, const int* in_sizes, int n_in,
                              void* d_out, int out_size) {
    const float* x  = (const float*)d_in[0];
    const void*  ei = d_in[1];
    const float* W2 = (const float*)d_in[2];
    const float* W3 = (const float*)d_in[3];
    float* out = (float*)d_out;

    int n_nodes = in_sizes[0] / C;
    int n_edges = in_sizes[1] / 2;

    if (n_nodes <= N_MAX && n_edges <= E_MAX) {
        void* cnt_ptr = nullptr;
        void* ovf_ptr = nullptr;
        cudaGetSymbolAddress(&cnt_ptr, g_cnt);
        cudaGetSymbolAddress(&ovf_ptr, g_ovf_cnt);
        cudaMemsetAsync(cnt_ptr, 0, (size_t)n_nodes * sizeof(int), 0);
        cudaMemsetAsync(ovf_ptr, 0, sizeof(int), 0);

        int n_f4 = n_nodes * (C / 4);
        prep_kernel<<<768, 256>>>(x, ei, n_edges, n_nodes, n_f4);

        int warps_per_block = 256 / 32;
        int blocks = (n_nodes + warps_per_block - 1) / warps_per_block;
        gather_kernel<<<blocks, 256>>>(x, W2, W3, out, n_nodes);
    } else {
        detect_idx_kernel<<<1, 32>>>(ei, n_nodes);
        cudaMemsetAsync(out, 0, (size_t)out_size * sizeof(float), 0);
        edge_scatter_kernel<<<2048, 256>>>(x, ei, W2, W3, out, n_edges);
    }
}

// round 17
// speedup vs baseline: 1.0486x; 1.0486x over previous
#include <cuda_runtime.h>
#include <cuda_fp16.h>
#include <cstdint>

#define C 128
#define N_MAX 16384
#define E_MAX 1100000
#define CAP 256
#define NB_CONVERT 128

// Static scratch (no allocs allowed)
__device__ int g_idx64;
__device__ int g_cnt[N_MAX];
__device__ int g_ssrc[N_MAX * CAP];           // bucketed src ids
__device__ int g_ovf_cnt;
__device__ long long g_ovf[E_MAX];            // overflow edges (dst<<32 | src)
__device__ __half g_xh[N_MAX * C];            // fp16 copy of x for gather stream

__global__ void detect_idx_kernel(const void* __restrict__ ei, int n_nodes) {
    if (threadIdx.x == 0 && blockIdx.x == 0) {
        const long long* p = (const long long*)ei;
        int ok = 1;
        #pragma unroll
        for (int i = 0; i < 16; i++) {
            long long v = p[i];
            if (v < 0 || v >= (long long)n_nodes) { ok = 0; }
        }
        g_idx64 = ok;
    }
}

__device__ __forceinline__ void bucket_put(int d, int s) {
    int pos = atomicAdd(&g_cnt[d], 1);
    if (pos < CAP) {
        g_ssrc[d * CAP + pos] = s;
    } else {
        int o = atomicAdd(&g_ovf_cnt, 1);
        g_ovf[o] = ((long long)d << 32) | (unsigned)s;
    }
}

// Role-split prep: blocks [0, NB_CONVERT) convert x fp32->fp16; the remaining
// blocks bucket edges by destination CONCURRENTLY (disjoint data; the kernel
// boundary before gather orders both against the consumer).
__global__ void prep_kernel(const float* __restrict__ x,
                            const void* __restrict__ ei,
                            int n_edges, int n_nodes, int n_f4) {
    if (blockIdx.x < NB_CONVERT) {
        // ---- convert role ----
        int gid = blockIdx.x * blockDim.x + threadIdx.x;
        int stride = NB_CONVERT * blockDim.x;
        for (int i = gid; i < n_f4; i += stride) {
            float4 v = __ldg((const float4*)x + i);
            __half2 h0 = __floats2half2_rn(v.x, v.y);
            __half2 h1 = __floats2half2_rn(v.z, v.w);
            uint2 u;
            u.x = *reinterpret_cast<unsigned*>(&h0);
            u.y = *reinterpret_cast<unsigned*>(&h1);
            ((uint2*)g_xh)[i] = u;
        }
        return;
    }

    // ---- bucket role ----
    __shared__ int s_idx64;
    if (threadIdx.x == 0) {
        const long long* p = (const long long*)ei;
        int ok = 1;
        #pragma unroll
        for (int i = 0; i < 16; i++) {
            long long v = p[i];
            if (v < 0 || v >= (long long)n_nodes) { ok = 0; }
        }
        s_idx64 = ok;
    }
    __syncthreads();
    const int idx64 = s_idx64;

    int gid = (blockIdx.x - NB_CONVERT) * blockDim.x + threadIdx.x;
    int stride = (gridDim.x - NB_CONVERT) * blockDim.x;

    const int npair = n_edges >> 1;
    if (idx64) {
        const longlong2* ps = (const longlong2*)ei;
        const longlong2* pd = (const longlong2*)((const long long*)ei + n_edges);
        for (int q = gid; q < npair; q += stride) {
            longlong2 sp = __ldg(ps + q);
            longlong2 dp = __ldg(pd + q);
            bucket_put((int)dp.x, (int)sp.x);
            bucket_put((int)dp.y, (int)sp.y);
        }
        if (gid == 0 && (n_edges & 1)) {
            int e = n_edges - 1;
            bucket_put((int)__ldg((const long long*)ei + n_edges + e),
                       (int)__ldg((const long long*)ei + e));
        }
    } else {
        const int2* ps = (const int2*)ei;
        const int2* pd = (const int2*)((const int*)ei + n_edges);
        for (int q = gid; q < npair; q += stride) {
            int2 sp = __ldg(ps + q);
            int2 dp = __ldg(pd + q);
            bucket_put(dp.x, sp.x);
            bucket_put(dp.y, sp.y);
        }
        if (gid == 0 && (n_edges & 1)) {
            int e = n_edges - 1;
            bucket_put(__ldg((const int*)ei + n_edges + e),
                       __ldg((const int*)ei + e));
        }
    }
}

// Transposed 4-value warp reduction: 10 SHFL for 4 independent sums.
__device__ __forceinline__ void reduce4(float p0, float p1, float p2, float p3,
                                        float& A0, float& A1, float& A2, float& A3,
                                        int lane)
{
    const unsigned FULL = 0xffffffffu;
    bool lo16 = (lane & 16) == 0;
    float q01 = (lo16 ? p0 : p1) + __shfl_xor_sync(FULL, lo16 ? p1 : p0, 16);
    float q23 = (lo16 ? p2 : p3) + __shfl_xor_sync(FULL, lo16 ? p3 : p2, 16);
    bool lo8 = (lane & 8) == 0;
    float r = (lo8 ? q01 : q23) + __shfl_xor_sync(FULL, lo8 ? q23 : q01, 8);
    r += __shfl_xor_sync(FULL, r, 4);
    r += __shfl_xor_sync(FULL, r, 2);
    r += __shfl_xor_sync(FULL, r, 1);
    A0 = __shfl_sync(FULL, r, 0);
    A2 = __shfl_sync(FULL, r, 8);
    A1 = __shfl_sync(FULL, r, 16);
    A3 = __shfl_sync(FULL, r, 24);
}

// One warp per destination node (R14 — proven best; byte-identical).
__global__ __launch_bounds__(256) void gather_kernel(
    const float* __restrict__ x,
    const float* __restrict__ W2,
    const float* __restrict__ W3,
    float* __restrict__ out,
    int n_nodes)
{
    const int lane = threadIdx.x & 31;
    const int j = (int)((blockIdx.x * (unsigned)blockDim.x + threadIdx.x) >> 5);
    if (j >= n_nodes) return;
    const unsigned FULL = 0xffffffffu;

    float4 xj = __ldg((const float4*)(x + (long long)j * C) + lane);
    float4 w3 = __ldg((const float4*)W3 + lane);
    float4 w3xj;
    w3xj.x = w3.x * xj.x; w3xj.y = w3.y * xj.y;
    w3xj.z = w3.z * xj.z; w3xj.w = w3.w * xj.w;

    float4 acc = make_float4(0.f, 0.f, 0.f, 0.f);

    const int deg_raw = __ldg(&g_cnt[j]);
    const int deg = (deg_raw > CAP) ? CAP : deg_raw;
    const int deg4 = deg & ~3;               // full quads
    const int* bucket = &g_ssrc[j * CAP];

    if (deg4 > 0) {
        int4 sv_nxt = __ldg((const int4*)bucket);
        uint2 uc0 = __ldg((const uint2*)(g_xh + (long long)sv_nxt.x * C) + lane);
        uint2 uc1 = __ldg((const uint2*)(g_xh + (long long)sv_nxt.y * C) + lane);
        uint2 uc2 = __ldg((const uint2*)(g_xh + (long long)sv_nxt.z * C) + lane);
        uint2 uc3 = __ldg((const uint2*)(g_xh + (long long)sv_nxt.w * C) + lane);
        sv_nxt = __ldg((const int4*)(bucket + ((4 < deg4) ? 4 : 0)));

        for (int i = 0; i < deg4; i += 4) {
            int pf = (i + 8 < deg4) ? (i + 8) : 0;
            int4 sv_fut = __ldg((const int4*)(bucket + pf));

            uint2 un0 = __ldg((const uint2*)(g_xh + (long long)sv_nxt.x * C) + lane);
            uint2 un1 = __ldg((const uint2*)(g_xh + (long long)sv_nxt.y * C) + lane);
            uint2 un2 = __ldg((const uint2*)(g_xh + (long long)sv_nxt.z * C) + lane);
            uint2 un3 = __ldg((const uint2*)(g_xh + (long long)sv_nxt.w * C) + lane);

            float2 a0 = __half22float2(*(__half2*)&uc0.x), b0 = __half22float2(*(__half2*)&uc0.y);
            float2 a1 = __half22float2(*(__half2*)&uc1.x), b1 = __half22float2(*(__half2*)&uc1.y);
            float2 a2 = __half22float2(*(__half2*)&uc2.x), b2 = __half22float2(*(__half2*)&uc2.y);
            float2 a3 = __half22float2(*(__half2*)&uc3.x), b3 = __half22float2(*(__half2*)&uc3.y);

            float p0 = a0.x * w3xj.x + a0.y * w3xj.y + b0.x * w3xj.z + b0.y * w3xj.w;
            float p1 = a1.x * w3xj.x + a1.y * w3xj.y + b1.x * w3xj.z + b1.y * w3xj.w;
            float p2 = a2.x * w3xj.x + a2.y * w3xj.y + b2.x * w3xj.z + b2.y * w3xj.w;
            float p3 = a3.x * w3xj.x + a3.y * w3xj.y + b3.x * w3xj.z + b3.y * w3xj.w;

            float A0, A1, A2, A3;
            reduce4(p0, p1, p2, p3, A0, A1, A2, A3, lane);

            acc.x += A0 * a0.x + A1 * a1.x + A2 * a2.x + A3 * a3.x;
            acc.y += A0 * a0.y + A1 * a1.y + A2 * a2.y + A3 * a3.y;
            acc.z += A0 * b0.x + A1 * b1.x + A2 * b2.x + A3 * b3.x;
            acc.w += A0 * b0.y + A1 * b1.y + A2 * b2.y + A3 * b3.y;

            uc0 = un0; uc1 = un1; uc2 = un2; uc3 = un3;
            sv_nxt = sv_fut;
        }
    }

    for (int i = deg4; i < deg; i++) {
        int s = __ldg(bucket + i);
        uint2 u0 = __ldg((const uint2*)(g_xh + (long long)s * C) + lane);
        float2 a0 = __half22float2(*(__half2*)&u0.x), b0 = __half22float2(*(__half2*)&u0.y);
        float p0 = a0.x * w3xj.x + a0.y * w3xj.y + b0.x * w3xj.z + b0.y * w3xj.w;
        #pragma unroll
        for (int o = 16; o > 0; o >>= 1)
            p0 += __shfl_xor_sync(FULL, p0, o);
        acc.x += p0 * a0.x; acc.y += p0 * a0.y;
        acc.z += p0 * b0.x; acc.w += p0 * b0.y;
    }

    if (deg_raw > CAP) {
        int n = g_ovf_cnt;
        for (int e2 = 0; e2 < n; e2++) {
            long long pk = g_ovf[e2];
            if ((int)(pk >> 32) != j) continue;
            int s = (int)(unsigned)(pk & 0xffffffffLL);
            uint2 u0 = __ldg((const uint2*)(g_xh + (long long)s * C) + lane);
            float2 a0 = __half22float2(*(__half2*)&u0.x), b0 = __half22float2(*(__half2*)&u0.y);
            float p0 = a0.x * w3xj.x + a0.y * w3xj.y + b0.x * w3xj.z + b0.y * w3xj.w;
            #pragma unroll
            for (int o = 16; o > 0; o >>= 1)
                p0 += __shfl_xor_sync(FULL, p0, o);
            acc.x += p0 * a0.x; acc.y += p0 * a0.y;
            acc.z += p0 * b0.x; acc.w += p0 * b0.y;
        }
    }

    float4 w2 = __ldg((const float4*)W2 + lane);
    float4 r;
    r.x = acc.x * w2.x; r.y = acc.y * w2.y;
    r.z = acc.z * w2.z; r.w = acc.w * w2.w;
    ((float4*)(out + (long long)j * C))[lane] = r;
}

// ---------------- Fallback (R5 kernel) for unexpected shapes ----------------
__global__ __launch_bounds__(256, 4) void edge_scatter_kernel(
    const float* __restrict__ x, const void* __restrict__ ei,
    const float* __restrict__ W2, const float* __restrict__ W3,
    float* __restrict__ out, int n_edges)
{
    const int lane = threadIdx.x & 31;
    const int t = lane & 7;
    const int grp = lane >> 3;
    const int warp_id = (int)((blockIdx.x * (unsigned)blockDim.x + threadIdx.x) >> 5);
    const int n_warps = (int)((gridDim.x * (unsigned)blockDim.x) >> 5);

    float4 w2v[4], w3v[4];
    #pragma unroll
    for (int k = 0; k < 4; k++) {
        w3v[k] = __ldg((const float4*)W3 + (t + 8 * k));
        w2v[k] = __ldg((const float4*)W2 + (t + 8 * k));
    }
    const int idx64 = g_idx64;
    const long long* p64 = (const long long*)ei;
    const int*       p32 = (const int*)ei;

    for (int base = warp_id * 4; base < n_edges; base += n_warps * 4) {
        int e = base + grp;
        bool valid = (e < n_edges);
        int ec = valid ? e : (n_edges - 1);
        long long src, dst;
        if (idx64) { src = __ldg(p64 + ec); dst = __ldg(p64 + n_edges + ec); }
        else { src = (long long)__ldg(p32 + ec); dst = (long long)__ldg(p32 + n_edges + ec); }

        const float4* srow = (const float4*)(x + src * C);
        const float4* drow = (const float4*)(x + dst * C);
        float4 vs[4], vd[4];
        #pragma unroll
        for (int k = 0; k < 4; k++) vs[k] = __ldg(srow + (t + 8 * k));
        #pragma unroll
        for (int k = 0; k < 4; k++) vd[k] = __ldg(drow + (t + 8 * k));

        float part = 0.f;
        #pragma unroll
        for (int k = 0; k < 4; k++)
            part += vs[k].x * w3v[k].x * vd[k].x + vs[k].y * w3v[k].y * vd[k].y
                  + vs[k].z * w3v[k].z * vd[k].z + vs[k].w * w3v[k].w * vd[k].w;
        part += __shfl_xor_sync(0xffffffffu, part, 4);
        part += __shfl_xor_sync(0xffffffffu, part, 2);
        part += __shfl_xor_sync(0xffffffffu, part, 1);

        if (valid) {
            float* op = out + dst * C;
            #pragma unroll
            for (int k = 0; k < 4; k++) {
                float4 r;
                r.x = part * vs[k].x * w2v[k].x; r.y = part * vs[k].y * w2v[k].y;
                r.z = part * vs[k].z * w2v[k].z; r.w = part * vs[k].w * w2v[k].w;
                asm volatile("red.global.add.v4.f32 [%0], {%1,%2,%3,%4};"
                             :: "l"(op + (t + 8 * k) * 4),
                                "f"(r.x), "f"(r.y), "f"(r.z), "f"(r.w) : "memory");
            }
        }
    }
}

extern "C" void kernel_launch(void* const* d_in, const int* in_sizes, int n_in,
                              void* d_out, int out_size) {
    const float* x  = (const float*)d_in[0];
    const void*  ei = d_in[1];
    const float* W2 = (const float*)d_in[2];
    const float* W3 = (const float*)d_in[3];
    float* out = (float*)d_out;

    int n_nodes = in_sizes[0] / C;
    int n_edges = in_sizes[1] / 2;

    if (n_nodes <= N_MAX && n_edges <= E_MAX) {
        void* cnt_ptr = nullptr;
        void* ovf_ptr = nullptr;
        cudaGetSymbolAddress(&cnt_ptr, g_cnt);
        cudaGetSymbolAddress(&ovf_ptr, g_ovf_cnt);
        cudaMemsetAsync(cnt_ptr, 0, (size_t)n_nodes * sizeof(int), 0);
        cudaMemsetAsync(ovf_ptr, 0, sizeof(int), 0);

        int n_f4 = n_nodes * (C / 4);
        prep_kernel<<<768, 256>>>(x, ei, n_edges, n_nodes, n_f4);

        int warps_per_block = 256 / 32;
        int blocks = (n_nodes + warps_per_block - 1) / warps_per_block;
        gather_kernel<<<blocks, 256>>>(x, W2, W3, out, n_nodes);
    } else {
        detect_idx_kernel<<<1, 32>>>(ei, n_nodes);
        cudaMemsetAsync(out, 0, (size_t)out_size * sizeof(float), 0);
        edge_scatter_kernel<<<2048, 256>>>(x, ei, W2, W3, out, n_edges);
    }
}